// round 9
// baseline (speedup 1.0000x reference)
#include <cuda_runtime.h>
#include <cuda_bf16.h>
#include <math.h>
#include <stdint.h>

#define BN_INV 0.9999950000374997f

// ---------------- scratch (device globals) -----------------------------------
__device__ __align__(16) uint32_t g_p1h[8*128*128*16], g_p1l[8*128*128*16];
__device__ __align__(16) uint32_t g_p2h[8*64*64*32],   g_p2l[8*64*64*32];
__device__ __align__(16) uint32_t g_p3h[8*32*32*64],   g_p3l[8*32*32*64];
__device__ __align__(16) uint16_t g_B2h[9*64*40],    g_B2l[9*64*40];
__device__ __align__(16) uint16_t g_B3h[36*64*40],   g_B3l[36*64*40];
__device__ __align__(16) uint16_t g_B4h[144*64*40],  g_B4l[144*64*40];
__device__ float g_e4[8*256*32*32];
__device__ float g_A [256*16*16];

// ---------------- helpers -----------------------------------------------------
__device__ __forceinline__ uint32_t smem_to_u32(const void* p) {
    uint32_t a;
    asm("{ .reg .u64 t; cvta.to.shared.u64 t, %1; cvt.u32.u64 %0, t; }" : "=r"(a) : "l"(p));
    return a;
}
#define LDSM4(r, a) \
    asm volatile("ldmatrix.sync.aligned.m8n8.x4.shared.b16 {%0,%1,%2,%3}, [%4];" \
        : "=r"((r)[0]), "=r"((r)[1]), "=r"((r)[2]), "=r"((r)[3]) : "r"(a))

__device__ __forceinline__ void mma16816(float* c, const uint32_t* a, uint32_t b0, uint32_t b1) {
    asm volatile(
        "mma.sync.aligned.m16n8k16.row.col.f32.bf16.bf16.f32 "
        "{%0,%1,%2,%3}, {%4,%5,%6,%7}, {%8,%9}, {%0,%1,%2,%3};"
        : "+f"(c[0]), "+f"(c[1]), "+f"(c[2]), "+f"(c[3])
        : "r"(a[0]), "r"(a[1]), "r"(a[2]), "r"(a[3]), "r"(b0), "r"(b1));
}

// split: hi = top-16 truncation of (a,b) packed; lo = rn(x - hi) packed bf16x2
__device__ __forceinline__ void split2(float a, float b, uint32_t& hi2, uint32_t& lo2) {
    uint32_t au = __float_as_uint(a), bu = __float_as_uint(b);
    hi2 = __byte_perm(au, bu, 0x7632);
    float la = a - __uint_as_float(au & 0xFFFF0000u);
    float lb = b - __uint_as_float(bu & 0xFFFF0000u);
    __nv_bfloat162 l2 = __floats2bfloat162_rn(la, lb);
    lo2 = *reinterpret_cast<uint32_t*>(&l2);
}

// ======================= conv1 + pool1 fused =================================
__global__ __launch_bounds__(256) void conv1_pool_kernel(
    const float* __restrict__ x, const float* __restrict__ w,
    const float* __restrict__ g, const float* __restrict__ b,
    float* __restrict__ out, uint32_t* __restrict__ oh, uint32_t* __restrict__ ol)
{
    __shared__ float ws[288], ss[32], bs[32];
    __shared__ float tile[18][66];
    const int tid = threadIdx.x;
    for (int i = tid; i < 288; i += 256) ws[i] = w[i];
    if (tid < 32) { ss[tid] = g[tid] * BN_INV; bs[tid] = b[tid]; }
    const int n = blockIdx.z, y0 = blockIdx.y * 16, x0 = blockIdx.x * 64;
    const float* xp = x + (long)n * 65536;
    for (int i = tid; i < 18 * 66; i += 256) {
        int r = i / 66, c = i % 66, yy = y0 - 1 + r, xx = x0 - 1 + c;
        tile[r][c] = (yy >= 0 && yy < 256 && xx >= 0 && xx < 256) ? xp[yy * 256 + xx] : 0.f;
    }
    __syncthreads();
    const int tx = tid & 15, ty = tid >> 4;
    float win[3][6];
#pragma unroll
    for (int r = 0; r < 3; r++)
#pragma unroll
        for (int c = 0; c < 6; c++) win[r][c] = tile[ty + r][tx * 4 + c];
    float* op = out + (long)n * 32 * 65536 + (y0 + ty) * 256 + x0 + tx * 4;

    const bool lowlane = ((tid & 31) < 16);
    const int yp = (y0 >> 1) + (ty >> 1);
    const int xp0 = (x0 >> 1) + tx * 2;
    const long pbase = (((long)n * 128 + yp) * 128 + xp0) * 16;

#pragma unroll
    for (int cb = 0; cb < 4; cb++) {
        float h0s[8], h1s[8];
#pragma unroll
        for (int c = 0; c < 8; c++) {
            int ch = cb * 8 + c;
            float acc0 = 0.f, acc1 = 0.f, acc2 = 0.f, acc3 = 0.f;
#pragma unroll
            for (int ky = 0; ky < 3; ky++)
#pragma unroll
                for (int kx = 0; kx < 3; kx++) {
                    float wv = ws[ch * 9 + ky * 3 + kx];
                    acc0 += wv * win[ky][kx + 0];
                    acc1 += wv * win[ky][kx + 1];
                    acc2 += wv * win[ky][kx + 2];
                    acc3 += wv * win[ky][kx + 3];
                }
            float s = ss[ch], bb = bs[ch];
            float4 v;
            v.x = fmaxf(acc0 * s + bb, 0.f); v.y = fmaxf(acc1 * s + bb, 0.f);
            v.z = fmaxf(acc2 * s + bb, 0.f); v.w = fmaxf(acc3 * s + bb, 0.f);
            *(float4*)(op + (long)ch * 65536) = v;
            h0s[c] = fmaxf(v.x, v.y);
            h1s[c] = fmaxf(v.z, v.w);
        }
#pragma unroll
        for (int c = 0; c < 8; c++) {
            float q0 = __shfl_xor_sync(0xffffffffu, h0s[c], 16);
            float q1 = __shfl_xor_sync(0xffffffffu, h1s[c], 16);
            h0s[c] = fmaxf(h0s[c], q0);
            h1s[c] = fmaxf(h1s[c], q1);
        }
        if (lowlane) {
            uint4 hv0, lv0, hv1, lv1;
            split2(h0s[0], h0s[1], hv0.x, lv0.x); split2(h0s[2], h0s[3], hv0.y, lv0.y);
            split2(h0s[4], h0s[5], hv0.z, lv0.z); split2(h0s[6], h0s[7], hv0.w, lv0.w);
            split2(h1s[0], h1s[1], hv1.x, lv1.x); split2(h1s[2], h1s[3], hv1.y, lv1.y);
            split2(h1s[4], h1s[5], hv1.z, lv1.z); split2(h1s[6], h1s[7], hv1.w, lv1.w);
            *(uint4*)(oh + pbase + cb * 4)      = hv0;
            *(uint4*)(ol + pbase + cb * 4)      = lv0;
            *(uint4*)(oh + pbase + 16 + cb * 4) = hv1;
            *(uint4*)(ol + pbase + 16 + cb * 4) = lv1;
        }
    }
}

// ======== pack all weights: uniform K=32 blocks, row stride 40 u16 ===========
// blk = (ocb*9+pos)*nkc+kc ; icg = kc*32+ic.
__device__ __forceinline__ void pack_one(const float* __restrict__ w, int e,
                                         int Cin, int nkc,
                                         uint16_t* __restrict__ oh, uint16_t* __restrict__ ol)
{
    int ic = e & 31;
    int t = e >> 5;
    int r = t % 64;
    int blk = t / 64;
    int kc = blk % nkc, t2 = blk / nkc;
    int pos = t2 % 9, ocb = t2 / 9;
    int icg = kc * 32 + ic, ocg = ocb * 64 + r;
    float v = w[((long)ocg * Cin + icg) * 9 + pos];
    uint32_t u = __float_as_uint(v);
    float vl = v - __uint_as_float(u & 0xFFFF0000u);
    long idx = (long)blk * 2560 + r * 40 + ic;
    oh[idx] = (uint16_t)(u >> 16);
    ol[idx] = __bfloat16_as_ushort(__float2bfloat16(vl));
}

__global__ void pack_all_kernel(
    const float* __restrict__ w2, const float* __restrict__ w3, const float* __restrict__ w4,
    uint16_t* __restrict__ B2h, uint16_t* __restrict__ B2l,
    uint16_t* __restrict__ B3h, uint16_t* __restrict__ B3l,
    uint16_t* __restrict__ B4h, uint16_t* __restrict__ B4l)
{
    int e = blockIdx.x * 256 + threadIdx.x;
    if (e < 18432)       pack_one(w2, e,          32, 1, B2h, B2l);
    else if (e < 92160)  pack_one(w3, e - 18432,  64, 2, B3h, B3l);
    else if (e < 387072) pack_one(w4, e - 92160, 128, 4, B4h, B4l);
}

// ======== pipelined mma.sync implicit-GEMM conv + fused 2x2 pool ==============
// Uniform K=32 phases, S = 3*nkc. 2-stage smem double buffer: gather phase s+1
// via cp.async overlaps MMA on phase s. CTA tile: rpt rows x TW cols (=128 px),
// N=64 oc. strideA = 80 B. Buffer = A(hi,lo) + B(3 taps, hi,lo).
__global__ __launch_bounds__(256) void conv_mma_kernel(
    const uint4* __restrict__ inh, const uint4* __restrict__ inl,
    const uint4* __restrict__ Bh, const uint4* __restrict__ Bl,
    const float* __restrict__ g, const float* __restrict__ b,
    float* __restrict__ out,
    int H, int W, int TWsh, int rpt, int CW4, int nkcsh, int Cout, int xstrips,
    uint32_t* __restrict__ ph, uint32_t* __restrict__ pl, int poolCW)
{
    extern __shared__ char sm[];
    const int TW = 1 << TWsh;
    const int Wp2 = TW + 2;
    const int rowsA = rpt * Wp2;
    const int nkc = 1 << nkcsh;
    const int S = 3 << nkcsh;
    const int ABytes = rowsA * 80;
    const int BUFSZ = 2 * ABytes + 30720;      // + B: 2*3*64*80
    const int tid = threadIdx.x;
    const int ocb = blockIdx.y, n = blockIdx.z;
    const int xt = blockIdx.x % xstrips, yt = blockIdx.x / xstrips;
    const int y0 = yt * rpt, x0 = xt << TWsh;

    float* ss = (float*)(sm + 2 * BUFSZ);
    float* bs = ss + 64;
    float* stage = (float*)sm;                 // reused after final sync

    if (tid < 64) { ss[tid] = g[ocb * 64 + tid] * BN_INV; bs[tid] = b[ocb * 64 + tid]; }

    const uint32_t smU = smem_to_u32(sm);
    const int lane = tid & 31, warp = tid >> 5;
    const int wm = warp & 3, wn = warp >> 2;
    const int mbase = wm * 32, nbase = wn * 32;
    const int arow = lane & 15, acol = (lane >> 4) * 16;
    const int brow = (lane & 7) + ((lane >> 4) << 3), bcol = ((lane >> 3) & 1) * 16;

    int aRowBase[2];
#pragma unroll
    for (int mt = 0; mt < 2; mt++) {
        int m = mbase + mt * 16 + arow;
        aRowBase[mt] = (m >> TWsh) * Wp2 + (m & (TW - 1));
    }

    float acc[2][4][4];
#pragma unroll
    for (int i = 0; i < 2; i++)
#pragma unroll
        for (int j = 0; j < 4; j++)
#pragma unroll
            for (int k = 0; k < 4; k++) acc[i][j][k] = 0.f;

    const int totA = rowsA * 4;                // uint4 per array

    auto issue_gather = [&](int s) {
        const int ky = s >> nkcsh, kc = s & (nkc - 1);
        const uint32_t bufU = smU + (s & 1) * BUFSZ;
        // A (hi + lo), zero-fill halo
        for (int i = tid; i < totA; i += 256) {
            int row = i >> 2, j = i & 3;
            int seg = row / Wp2;
            int px = x0 + (row - seg * Wp2) - 1;
            int py = y0 + seg + ky - 1;
            bool ok = ((unsigned)px < (unsigned)W) && ((unsigned)py < (unsigned)H);
            long src = (((long)n * H + py) * W + px) * CW4 + kc * 4 + j;
            uint32_t dA = bufU + (uint32_t)(row * 80 + j * 16);
            int sz = ok ? 16 : 0;
            asm volatile("cp.async.cg.shared.global [%0], [%1], 16, %2;"
                         :: "r"(dA), "l"(inh + src), "r"(sz) : "memory");
            asm volatile("cp.async.cg.shared.global [%0], [%1], 16, %2;"
                         :: "r"(dA + (uint32_t)ABytes), "l"(inl + src), "r"(sz) : "memory");
        }
        // B: 3 kx taps (320 uint4 each per array)
        const int blk0 = (ocb * 9 + ky * 3) * nkc + kc;
        const uint32_t bB = bufU + (uint32_t)(2 * ABytes);
        for (int i = tid; i < 960; i += 256) {
            int tap = i / 320, r = i - tap * 320;
            long gsrc = (long)(blk0 + tap * nkc) * 320 + r;
            uint32_t dB = bB + (uint32_t)i * 16;
            asm volatile("cp.async.cg.shared.global [%0], [%1], 16;"
                         :: "r"(dB), "l"(Bh + gsrc) : "memory");
            asm volatile("cp.async.cg.shared.global [%0], [%1], 16;"
                         :: "r"(dB + 15360u), "l"(Bl + gsrc) : "memory");
        }
        asm volatile("cp.async.commit_group;" ::: "memory");
    };

    issue_gather(0);
    for (int s = 0; s < S; s++) {
        if (s + 1 < S) {
            issue_gather(s + 1);
            asm volatile("cp.async.wait_group 1;" ::: "memory");
        } else {
            asm volatile("cp.async.wait_group 0;" ::: "memory");
        }
        __syncthreads();   // buffer s visible to all

        const uint32_t AhU = smU + (s & 1) * BUFSZ;
        const uint32_t BhU = AhU + (uint32_t)(2 * ABytes);
        for (int kx = 0; kx < 3; kx++) {
#pragma unroll
            for (int k16 = 0; k16 < 2; k16++) {
                uint32_t ah[2][4], al[2][4], bh[2][4], bl[2][4];
#pragma unroll
                for (int mt = 0; mt < 2; mt++) {
                    uint32_t aaddr = AhU + (uint32_t)(aRowBase[mt] + kx) * 80
                                   + k16 * 32 + acol;
                    LDSM4(ah[mt], aaddr);
                    LDSM4(al[mt], aaddr + (uint32_t)ABytes);
                }
#pragma unroll
                for (int g2 = 0; g2 < 2; g2++) {
                    uint32_t baddr = BhU + (uint32_t)(kx * 64 + nbase + g2 * 16 + brow) * 80
                                   + k16 * 32 + bcol;
                    LDSM4(bh[g2], baddr);
                    LDSM4(bl[g2], baddr + 15360u);
                }
#pragma unroll
                for (int mt = 0; mt < 2; mt++)
#pragma unroll
                    for (int nt = 0; nt < 4; nt++) {
                        const int g2 = nt >> 1, pr = (nt & 1) * 2;
                        mma16816(acc[mt][nt], ah[mt], bh[g2][pr], bh[g2][pr + 1]);
                        mma16816(acc[mt][nt], ah[mt], bl[g2][pr], bl[g2][pr + 1]);
                        mma16816(acc[mt][nt], al[mt], bh[g2][pr], bh[g2][pr + 1]);
                    }
            }
        }
        __syncthreads();   // all reads of buffer s done before gather s+2 overwrites
    }

    // ---- epilogue: stage ([oc][pixel], stride 132) ----
    {
        const int r0 = lane >> 2, cpair = (lane & 3) * 2;
#pragma unroll
        for (int mt = 0; mt < 2; mt++) {
            const int m1 = mbase + mt * 16 + r0, m2 = m1 + 8;
#pragma unroll
            for (int nt = 0; nt < 4; nt++) {
                const int nc = nbase + nt * 8 + cpair;
                stage[nc * 132 + m1]       = acc[mt][nt][0];
                stage[(nc + 1) * 132 + m1] = acc[mt][nt][1];
                stage[nc * 132 + m2]       = acc[mt][nt][2];
                stage[(nc + 1) * 132 + m2] = acc[mt][nt][3];
            }
        }
    }
    __syncthreads();
    // coalesced NCHW stores
    {
        const long HW = (long)H * W;
        const long obase = ((long)n * Cout + ocb * 64) * HW;
        for (int i = tid; i < 8192; i += 256) {
            int oc = i >> 7, p = i & 127;
            int y = y0 + (p >> TWsh), x = x0 + (p & (TW - 1));
            float v = fmaxf(stage[oc * 132 + p] * ss[oc] + bs[oc], 0.f);
            out[obase + (long)oc * HW + (long)y * W + x] = v;
        }
    }
    // fused 2x2 pool -> NHWC bf16 hi/lo (rpt==2 tiles only)
    if (ph) {
        const int Hp = H >> 1, Wp = W >> 1;
        const int yp = y0 >> 1, xp0 = x0 >> 1;
        for (int i = tid; i < 1024; i += 256) {
            int cw = i & 31, xx = i >> 5;
            int c0 = cw * 2, c1 = c0 + 1;
            int pa = 2 * xx, pc = TW + 2 * xx;
            float m0 = fmaxf(fmaxf(stage[c0 * 132 + pa], stage[c0 * 132 + pa + 1]),
                             fmaxf(stage[c0 * 132 + pc], stage[c0 * 132 + pc + 1]));
            float m1 = fmaxf(fmaxf(stage[c1 * 132 + pa], stage[c1 * 132 + pa + 1]),
                             fmaxf(stage[c1 * 132 + pc], stage[c1 * 132 + pc + 1]));
            float v0 = fmaxf(m0 * ss[c0] + bs[c0], 0.f);
            float v1 = fmaxf(m1 * ss[c1] + bs[c1], 0.f);
            uint32_t hw, lw;
            split2(v0, v1, hw, lw);
            long o = (((long)n * Hp + yp) * Wp + xp0 + xx) * poolCW + ocb * 32 + cw;
            ph[o] = hw; pl[o] = lw;
        }
    }
}

// ---------------- build per-channel quadratic form A = Re(U^H diag(zbar) U) --
__global__ void build_A_kernel(const float* __restrict__ w0,
                               const float* __restrict__ w1,
                               float* __restrict__ A)
{
    int t = blockIdx.x * blockDim.x + threadIdx.x;
    if (t >= 256 * 16) return;
    int c = t >> 4, k = t & 15;
    float gr[4][2][2], gi[4][2][2];
    float a0 = w0[c*2+0], a1 = w0[c*2+1], z0 = w1[c*2+0], z1 = w1[c*2+1];
    const float isq2 = 0.7071067811865476f;
#pragma unroll
    for (int w = 0; w < 4; w++) {
        float ay = (w & 1) ? a1 : a0, az = (w & 1) ? z1 : z0;
        float cy = cosf(ay*0.5f), sy = sinf(ay*0.5f);
        float cz = cosf(az*0.5f), sz = sinf(az*0.5f);
        float m00 = (cy-sy)*isq2, m01 = (cy+sy)*isq2;
        float m10 = (sy+cy)*isq2, m11 = (sy-cy)*isq2;
        gr[w][0][0]=m00*cz; gi[w][0][0]=-m00*sz;
        gr[w][0][1]=m01*cz; gi[w][0][1]=-m01*sz;
        gr[w][1][0]=m10*cz; gi[w][1][0]= m10*sz;
        gr[w][1][1]=m11*cz; gi[w][1][1]= m11*sz;
    }
    int P[16];
#pragma unroll
    for (int bb = 0; bb < 16; bb++) {
        int v = bb;
        if (v & 1) v ^= 8;
        if (v & 2) v ^= 1;
        if (v & 4) v ^= 2;
        if (v & 8) v ^= 4;
        P[bb] = v;
    }
    float acc[16];
#pragma unroll
    for (int j = 0; j < 16; j++) acc[j] = 0.f;
    for (int i = 0; i < 16; i++) {
        int r = P[i];
        float zi = (4 - 2 * __popc(i)) * 0.25f;
        int r0=(r>>3)&1, r1=(r>>2)&1, r2=(r>>1)&1, r3=r&1;
        float t2r[2], t2i[2];
        t2r[0]=gr[0][r0][0]; t2i[0]=gi[0][r0][0];
        t2r[1]=gr[0][r0][1]; t2i[1]=gi[0][r0][1];
        float t4r[4], t4i[4];
#pragma unroll
        for (int j0 = 0; j0 < 2; j0++)
#pragma unroll
            for (int j1 = 0; j1 < 2; j1++) {
                float br=gr[1][r1][j1], bi=gi[1][r1][j1];
                t4r[j0*2+j1]=t2r[j0]*br-t2i[j0]*bi;
                t4i[j0*2+j1]=t2r[j0]*bi+t2i[j0]*br;
            }
        float t8r[8], t8i[8];
#pragma unroll
        for (int j = 0; j < 4; j++)
#pragma unroll
            for (int j2 = 0; j2 < 2; j2++) {
                float br=gr[2][r2][j2], bi=gi[2][r2][j2];
                t8r[j*2+j2]=t4r[j]*br-t4i[j]*bi;
                t8i[j*2+j2]=t4r[j]*bi+t4i[j]*br;
            }
        float ur[16], ui[16];
#pragma unroll
        for (int j = 0; j < 8; j++)
#pragma unroll
            for (int j3 = 0; j3 < 2; j3++) {
                float br=gr[3][r3][j3], bi=gi[3][r3][j3];
                ur[j*2+j3]=t8r[j]*br-t8i[j]*bi;
                ui[j*2+j3]=t8r[j]*bi+t8i[j]*br;
            }
        float ukr = ur[k], uki = ui[k];
#pragma unroll
        for (int j = 0; j < 16; j++)
            acc[j] += zi * (ur[j]*ukr + ui[j]*uki);
    }
#pragma unroll
    for (int j = 0; j < 16; j++) A[c*256 + j*16 + k] = acc[j];
}

// ---------------- quantum stage + BN5 + ReLU (fused) -------------------------
__global__ __launch_bounds__(256) void quantum_kernel(
    const float* __restrict__ e4, const float* __restrict__ A,
    const float* __restrict__ g5, const float* __restrict__ b5,
    float* __restrict__ out)
{
    __shared__ float tile[35 * 37];
    __shared__ float As[256];
    const int bc = blockIdx.x, c = bc & 255, tid = threadIdx.x;
    for (int i = tid; i < 35 * 37; i += 256) tile[i] = 0.f;
    __syncthreads();
    const float* ep = e4 + (long)bc * 1024;
    for (int i = tid; i < 1024; i += 256) {
        int r = i >> 5, cc = i & 31;
        tile[(r + 1) * 37 + (cc + 1)] = ep[i];
    }
    if (tid < 256) As[tid] = A[c * 256 + tid];
    __syncthreads();
    const int y = tid >> 3, x4 = (tid & 7) * 4;
    float win[4][7];
#pragma unroll
    for (int r = 0; r < 4; r++)
#pragma unroll
        for (int cc = 0; cc < 7; cc++) win[r][cc] = tile[(y + r) * 37 + x4 + cc];
    float s[4] = {0.f, 0.f, 0.f, 0.f};
#pragma unroll
    for (int o = 0; o < 4; o++)
#pragma unroll
        for (int t = 0; t < 16; t++) {
            float v = win[t >> 2][(t & 3) + o];
            s[o] += v * v;
        }
    float quad[4] = {0.f, 0.f, 0.f, 0.f};
#pragma unroll
    for (int j = 0; j < 16; j++) {
        float t0 = 0.f, t1 = 0.f, t2 = 0.f, t3 = 0.f;
        int jr = j >> 2, jc = j & 3;
#pragma unroll
        for (int k = 0; k < 16; k++) {
            float a = As[j * 16 + k];
            int kr = k >> 2, kc = k & 3;
            t0 += a * win[kr][kc + 0];
            t1 += a * win[kr][kc + 1];
            t2 += a * win[kr][kc + 2];
            t3 += a * win[kr][kc + 3];
        }
        quad[0] += t0 * win[jr][jc + 0];
        quad[1] += t1 * win[jr][jc + 1];
        quad[2] += t2 * win[jr][jc + 2];
        quad[3] += t3 * win[jr][jc + 3];
    }
    const float sc = g5[c] * BN_INV, bb = b5[c];
    float4 v;
    v.x = fmaxf((0.5f*quad[0]/fmaxf(s[0],1e-24f)+0.5f)*sc+bb, 0.f);
    v.y = fmaxf((0.5f*quad[1]/fmaxf(s[1],1e-24f)+0.5f)*sc+bb, 0.f);
    v.z = fmaxf((0.5f*quad[2]/fmaxf(s[2],1e-24f)+0.5f)*sc+bb, 0.f);
    v.w = fmaxf((0.5f*quad[3]/fmaxf(s[3],1e-24f)+0.5f)*sc+bb, 0.f);
    *(float4*)(out + (long)bc * 1024 + y * 32 + x4) = v;
}

// -----------------------------------------------------------------------------
// dyn smem: conv2/3 104192, conv4 105472
extern "C" void kernel_launch(void* const* d_in, const int* in_sizes, int n_in,
                              void* d_out, int out_size)
{
    (void)in_sizes; (void)n_in; (void)out_size;
    const float* x   = (const float*)d_in[0];
    const float* w1  = (const float*)d_in[1];
    const float* g1  = (const float*)d_in[2];
    const float* b1  = (const float*)d_in[3];
    const float* w2  = (const float*)d_in[4];
    const float* g2  = (const float*)d_in[5];
    const float* b2  = (const float*)d_in[6];
    const float* w3  = (const float*)d_in[7];
    const float* g3  = (const float*)d_in[8];
    const float* b3  = (const float*)d_in[9];
    const float* w4  = (const float*)d_in[10];
    const float* g4  = (const float*)d_in[11];
    const float* b4  = (const float*)d_in[12];
    const float* qw0 = (const float*)d_in[13];
    const float* qw1 = (const float*)d_in[14];
    const float* g5  = (const float*)d_in[15];
    const float* b5  = (const float*)d_in[16];

    float* out = (float*)d_out;
    float* e1 = out;
    float* e2 = out + 16777216;
    float* e3 = out + 25165824;
    float* o4 = out + 29360128;

    uint32_t *p1h, *p1l, *p2h, *p2l, *p3h, *p3l;
    uint16_t *B2h, *B2l, *B3h, *B3l, *B4h, *B4l;
    float *e4, *Ab;
    cudaGetSymbolAddress((void**)&p1h, g_p1h); cudaGetSymbolAddress((void**)&p1l, g_p1l);
    cudaGetSymbolAddress((void**)&p2h, g_p2h); cudaGetSymbolAddress((void**)&p2l, g_p2l);
    cudaGetSymbolAddress((void**)&p3h, g_p3h); cudaGetSymbolAddress((void**)&p3l, g_p3l);
    cudaGetSymbolAddress((void**)&B2h, g_B2h); cudaGetSymbolAddress((void**)&B2l, g_B2l);
    cudaGetSymbolAddress((void**)&B3h, g_B3h); cudaGetSymbolAddress((void**)&B3l, g_B3l);
    cudaGetSymbolAddress((void**)&B4h, g_B4h); cudaGetSymbolAddress((void**)&B4l, g_B4l);
    cudaGetSymbolAddress((void**)&e4, g_e4);   cudaGetSymbolAddress((void**)&Ab, g_A);

    cudaFuncSetAttribute(conv_mma_kernel, cudaFuncAttributeMaxDynamicSharedMemorySize, 105472);

    // conv1 + pool1 fused -> e1, p1
    conv1_pool_kernel<<<dim3(4, 16, 8), 256>>>(x, w1, g1, b1, e1, p1h, p1l);
    // weight packing (single launch)
    pack_all_kernel<<<1512, 256>>>(w2, w3, w4, B2h, B2l, B3h, B3l, B4h, B4l);
    // conv2 -> e2 (8,64,128,128), fused pool2 -> p2 (NHWC 64ch @64x64)
    conv_mma_kernel<<<dim3(128, 1, 8), 256, 104192>>>(
        (const uint4*)p1h, (const uint4*)p1l, (const uint4*)B2h, (const uint4*)B2l,
        g2, b2, e2, 128, 128, 6, 2, 4, 0, 64, 2, p2h, p2l, 32);
    // conv3 -> e3 (8,128,64,64), fused pool3 -> p3 (NHWC 128ch @32x32)
    conv_mma_kernel<<<dim3(32, 2, 8), 256, 104192>>>(
        (const uint4*)p2h, (const uint4*)p2l, (const uint4*)B3h, (const uint4*)B3l,
        g3, b3, e3, 64, 64, 6, 2, 8, 1, 128, 1, p3h, p3l, 64);
    // conv4 -> e4 (8,256,32,32), no pool
    conv_mma_kernel<<<dim3(8, 4, 8), 256, 105472>>>(
        (const uint4*)p3h, (const uint4*)p3l, (const uint4*)B4h, (const uint4*)B4l,
        g4, b4, e4, 32, 32, 5, 4, 16, 2, 256, 1, (uint32_t*)0, (uint32_t*)0, 0);
    // quantum
    build_A_kernel<<<16, 256>>>(qw0, qw1, Ab);
    quantum_kernel<<<2048, 256>>>(e4, Ab, g5, b5, o4);
}

// round 10
// speedup vs baseline: 1.0559x; 1.0559x over previous
#include <cuda_runtime.h>
#include <cuda_bf16.h>
#include <math.h>
#include <stdint.h>

#define BN_INV 0.9999950000374997f

// ---------------- scratch (device globals) -----------------------------------
__device__ __align__(16) uint32_t g_p1h[8*128*128*16], g_p1l[8*128*128*16];
__device__ __align__(16) uint32_t g_p2h[8*64*64*32],   g_p2l[8*64*64*32];
__device__ __align__(16) uint32_t g_p3h[8*32*32*64],   g_p3l[8*32*32*64];
__device__ __align__(16) uint16_t g_B2h[9*64*40],    g_B2l[9*64*40];
__device__ __align__(16) uint16_t g_B3h[36*64*40],   g_B3l[36*64*40];
__device__ __align__(16) uint16_t g_B4h[144*64*40],  g_B4l[144*64*40];
__device__ float g_e4[8*256*32*32];
__device__ float g_A [256*16*16];

// ---------------- helpers -----------------------------------------------------
__device__ __forceinline__ uint32_t smem_to_u32(const void* p) {
    uint32_t a;
    asm("{ .reg .u64 t; cvta.to.shared.u64 t, %1; cvt.u32.u64 %0, t; }" : "=r"(a) : "l"(p));
    return a;
}
#define LDSM4(r, a) \
    asm volatile("ldmatrix.sync.aligned.m8n8.x4.shared.b16 {%0,%1,%2,%3}, [%4];" \
        : "=r"((r)[0]), "=r"((r)[1]), "=r"((r)[2]), "=r"((r)[3]) : "r"(a))

__device__ __forceinline__ void mma16816(float* c, const uint32_t* a, uint32_t b0, uint32_t b1) {
    asm volatile(
        "mma.sync.aligned.m16n8k16.row.col.f32.bf16.bf16.f32 "
        "{%0,%1,%2,%3}, {%4,%5,%6,%7}, {%8,%9}, {%0,%1,%2,%3};"
        : "+f"(c[0]), "+f"(c[1]), "+f"(c[2]), "+f"(c[3])
        : "r"(a[0]), "r"(a[1]), "r"(a[2]), "r"(a[3]), "r"(b0), "r"(b1));
}

// split: hi = top-16 truncation of (a,b) packed; lo = rn(x - hi) packed bf16x2
__device__ __forceinline__ void split2(float a, float b, uint32_t& hi2, uint32_t& lo2) {
    uint32_t au = __float_as_uint(a), bu = __float_as_uint(b);
    hi2 = __byte_perm(au, bu, 0x7632);
    float la = a - __uint_as_float(au & 0xFFFF0000u);
    float lb = b - __uint_as_float(bu & 0xFFFF0000u);
    __nv_bfloat162 l2 = __floats2bfloat162_rn(la, lb);
    lo2 = *reinterpret_cast<uint32_t*>(&l2);
}

// ======================= conv1 + pool1 fused =================================
__global__ __launch_bounds__(256) void conv1_pool_kernel(
    const float* __restrict__ x, const float* __restrict__ w,
    const float* __restrict__ g, const float* __restrict__ b,
    float* __restrict__ out, uint32_t* __restrict__ oh, uint32_t* __restrict__ ol)
{
    __shared__ float ws[288], ss[32], bs[32];
    __shared__ float tile[18][66];
    const int tid = threadIdx.x;
    for (int i = tid; i < 288; i += 256) ws[i] = w[i];
    if (tid < 32) { ss[tid] = g[tid] * BN_INV; bs[tid] = b[tid]; }
    const int n = blockIdx.z, y0 = blockIdx.y * 16, x0 = blockIdx.x * 64;
    const float* xp = x + (long)n * 65536;
    for (int i = tid; i < 18 * 66; i += 256) {
        int r = i / 66, c = i % 66, yy = y0 - 1 + r, xx = x0 - 1 + c;
        tile[r][c] = (yy >= 0 && yy < 256 && xx >= 0 && xx < 256) ? xp[yy * 256 + xx] : 0.f;
    }
    __syncthreads();
    const int tx = tid & 15, ty = tid >> 4;
    float win[3][6];
#pragma unroll
    for (int r = 0; r < 3; r++)
#pragma unroll
        for (int c = 0; c < 6; c++) win[r][c] = tile[ty + r][tx * 4 + c];
    float* op = out + (long)n * 32 * 65536 + (y0 + ty) * 256 + x0 + tx * 4;

    const bool lowlane = ((tid & 31) < 16);
    const int yp = (y0 >> 1) + (ty >> 1);
    const int xp0 = (x0 >> 1) + tx * 2;
    const long pbase = (((long)n * 128 + yp) * 128 + xp0) * 16;

#pragma unroll
    for (int cb = 0; cb < 4; cb++) {
        float h0s[8], h1s[8];
#pragma unroll
        for (int c = 0; c < 8; c++) {
            int ch = cb * 8 + c;
            float acc0 = 0.f, acc1 = 0.f, acc2 = 0.f, acc3 = 0.f;
#pragma unroll
            for (int ky = 0; ky < 3; ky++)
#pragma unroll
                for (int kx = 0; kx < 3; kx++) {
                    float wv = ws[ch * 9 + ky * 3 + kx];
                    acc0 += wv * win[ky][kx + 0];
                    acc1 += wv * win[ky][kx + 1];
                    acc2 += wv * win[ky][kx + 2];
                    acc3 += wv * win[ky][kx + 3];
                }
            float s = ss[ch], bb = bs[ch];
            float4 v;
            v.x = fmaxf(acc0 * s + bb, 0.f); v.y = fmaxf(acc1 * s + bb, 0.f);
            v.z = fmaxf(acc2 * s + bb, 0.f); v.w = fmaxf(acc3 * s + bb, 0.f);
            *(float4*)(op + (long)ch * 65536) = v;
            h0s[c] = fmaxf(v.x, v.y);
            h1s[c] = fmaxf(v.z, v.w);
        }
#pragma unroll
        for (int c = 0; c < 8; c++) {
            float q0 = __shfl_xor_sync(0xffffffffu, h0s[c], 16);
            float q1 = __shfl_xor_sync(0xffffffffu, h1s[c], 16);
            h0s[c] = fmaxf(h0s[c], q0);
            h1s[c] = fmaxf(h1s[c], q1);
        }
        if (lowlane) {
            uint4 hv0, lv0, hv1, lv1;
            split2(h0s[0], h0s[1], hv0.x, lv0.x); split2(h0s[2], h0s[3], hv0.y, lv0.y);
            split2(h0s[4], h0s[5], hv0.z, lv0.z); split2(h0s[6], h0s[7], hv0.w, lv0.w);
            split2(h1s[0], h1s[1], hv1.x, lv1.x); split2(h1s[2], h1s[3], hv1.y, lv1.y);
            split2(h1s[4], h1s[5], hv1.z, lv1.z); split2(h1s[6], h1s[7], hv1.w, lv1.w);
            *(uint4*)(oh + pbase + cb * 4)      = hv0;
            *(uint4*)(ol + pbase + cb * 4)      = lv0;
            *(uint4*)(oh + pbase + 16 + cb * 4) = hv1;
            *(uint4*)(ol + pbase + 16 + cb * 4) = lv1;
        }
    }
}

// ======== pack all weights: uniform K=32 blocks, row stride 40 u16 ===========
__device__ __forceinline__ void pack_one(const float* __restrict__ w, int e,
                                         int Cin, int nkc,
                                         uint16_t* __restrict__ oh, uint16_t* __restrict__ ol)
{
    int ic = e & 31;
    int t = e >> 5;
    int r = t % 64;
    int blk = t / 64;
    int kc = blk % nkc, t2 = blk / nkc;
    int pos = t2 % 9, ocb = t2 / 9;
    int icg = kc * 32 + ic, ocg = ocb * 64 + r;
    float v = w[((long)ocg * Cin + icg) * 9 + pos];
    uint32_t u = __float_as_uint(v);
    float vl = v - __uint_as_float(u & 0xFFFF0000u);
    long idx = (long)blk * 2560 + r * 40 + ic;
    oh[idx] = (uint16_t)(u >> 16);
    ol[idx] = __bfloat16_as_ushort(__float2bfloat16(vl));
}

__global__ void pack_all_kernel(
    const float* __restrict__ w2, const float* __restrict__ w3, const float* __restrict__ w4,
    uint16_t* __restrict__ B2h, uint16_t* __restrict__ B2l,
    uint16_t* __restrict__ B3h, uint16_t* __restrict__ B3l,
    uint16_t* __restrict__ B4h, uint16_t* __restrict__ B4l)
{
    int e = blockIdx.x * 256 + threadIdx.x;
    if (e < 18432)       pack_one(w2, e,          32, 1, B2h, B2l);
    else if (e < 92160)  pack_one(w3, e - 18432,  64, 2, B3h, B3l);
    else if (e < 387072) pack_one(w4, e - 92160, 128, 4, B4h, B4l);
}

// ======== mma.sync implicit-GEMM conv, kc-major A reuse, 3 CTA/SM =============
// Per kc: gather A ONCE covering rpt+2 input rows (all 3 ky taps read the same
// buffer at +ky*Wp2). B single-buffered per (ky,kc), loaded after the previous
// ky's MMAs complete. Small footprint (73.5KB) + reg cap -> 3 CTAs/SM.
__global__ __launch_bounds__(256, 3) void conv_mma_kernel(
    const uint4* __restrict__ inh, const uint4* __restrict__ inl,
    const uint4* __restrict__ Bh, const uint4* __restrict__ Bl,
    const float* __restrict__ g, const float* __restrict__ b,
    float* __restrict__ out,
    int H, int W, int TWsh, int rpt, int CW4, int nkcsh, int Cout, int xstrips,
    uint32_t* __restrict__ ph, uint32_t* __restrict__ pl, int poolCW)
{
    extern __shared__ char sm[];
    const int TW = 1 << TWsh;
    const int Wp2 = TW + 2;
    const int segs = rpt + 2;
    const int rowsA = segs * Wp2;
    const int ABytes = rowsA * 80;             // per array (hi or lo)
    const int nkc = 1 << nkcsh;
    const int tid = threadIdx.x;
    const int ocb = blockIdx.y, n = blockIdx.z;
    const int xt = blockIdx.x % xstrips, yt = blockIdx.x / xstrips;
    const int y0 = yt * rpt, x0 = xt << TWsh;

    float* ss = (float*)(sm + 2 * ABytes + 30720);
    float* bs = ss + 64;
    float* stage = (float*)sm;                 // reused after final sync

    if (tid < 64) { ss[tid] = g[ocb * 64 + tid] * BN_INV; bs[tid] = b[ocb * 64 + tid]; }

    const uint32_t AhU = smem_to_u32(sm);
    const uint32_t BhU = AhU + (uint32_t)(2 * ABytes);
    const int lane = tid & 31, warp = tid >> 5;
    const int wm = warp & 3, wn = warp >> 2;
    const int mbase = wm * 32, nbase = wn * 32;
    const int arow = lane & 15, acol = (lane >> 4) * 16;
    const int brow = (lane & 7) + ((lane >> 4) << 3), bcol = ((lane >> 3) & 1) * 16;

    int aRowBase[2];
#pragma unroll
    for (int mt = 0; mt < 2; mt++) {
        int m = mbase + mt * 16 + arow;
        aRowBase[mt] = (m >> TWsh) * Wp2 + (m & (TW - 1));
    }

    float acc[2][4][4];
#pragma unroll
    for (int i = 0; i < 2; i++)
#pragma unroll
        for (int j = 0; j < 4; j++)
#pragma unroll
            for (int k = 0; k < 4; k++) acc[i][j][k] = 0.f;

    const int totA = rowsA * 4;                // uint4 per array

    // --- prologue loads: A(kc=0) + B(ky=0,kc=0) ---
    {
        for (int i = tid; i < totA; i += 256) {
            int row = i >> 2, j = i & 3;
            int seg = row / Wp2;
            int px = x0 + (row - seg * Wp2) - 1;
            int py = y0 + seg - 1;
            bool ok = ((unsigned)px < (unsigned)W) && ((unsigned)py < (unsigned)H);
            long src = (((long)n * H + py) * W + px) * CW4 + j;
            uint32_t dA = AhU + (uint32_t)(row * 80 + j * 16);
            int sz = ok ? 16 : 0;
            asm volatile("cp.async.cg.shared.global [%0], [%1], 16, %2;"
                         :: "r"(dA), "l"(inh + src), "r"(sz) : "memory");
            asm volatile("cp.async.cg.shared.global [%0], [%1], 16, %2;"
                         :: "r"(dA + (uint32_t)ABytes), "l"(inl + src), "r"(sz) : "memory");
        }
        const int blk0 = (ocb * 9) * nkc;      // ky=0, kc=0
        for (int i = tid; i < 960; i += 256) {
            int tap = i / 320, r = i - tap * 320;
            long gsrc = (long)(blk0 + tap * nkc) * 320 + r;
            uint32_t dB = BhU + (uint32_t)i * 16;
            asm volatile("cp.async.cg.shared.global [%0], [%1], 16;"
                         :: "r"(dB), "l"(Bh + gsrc) : "memory");
            asm volatile("cp.async.cg.shared.global [%0], [%1], 16;"
                         :: "r"(dB + 15360u), "l"(Bl + gsrc) : "memory");
        }
        asm volatile("cp.async.commit_group;" ::: "memory");
    }

    for (int kc = 0; kc < nkc; kc++) {
        for (int ky = 0; ky < 3; ky++) {
            asm volatile("cp.async.wait_group 0;" ::: "memory");
            __syncthreads();   // loads visible; all warps past previous phase

            // ---- MMA: 3 kx taps x 2 k16 on resident A(kc), B(ky,kc) ----
            const int kyOff = ky * Wp2;
            for (int kx = 0; kx < 3; kx++) {
#pragma unroll
                for (int k16 = 0; k16 < 2; k16++) {
                    uint32_t ah[2][4], al[2][4], bh[2][4], bl[2][4];
#pragma unroll
                    for (int mt = 0; mt < 2; mt++) {
                        uint32_t aaddr = AhU + (uint32_t)(aRowBase[mt] + kyOff + kx) * 80
                                       + k16 * 32 + acol;
                        LDSM4(ah[mt], aaddr);
                        LDSM4(al[mt], aaddr + (uint32_t)ABytes);
                    }
#pragma unroll
                    for (int g2 = 0; g2 < 2; g2++) {
                        uint32_t baddr = BhU + (uint32_t)(kx * 64 + nbase + g2 * 16 + brow) * 80
                                       + k16 * 32 + bcol;
                        LDSM4(bh[g2], baddr);
                        LDSM4(bl[g2], baddr + 15360u);
                    }
#pragma unroll
                    for (int mt = 0; mt < 2; mt++)
#pragma unroll
                        for (int nt = 0; nt < 4; nt++) {
                            const int g2 = nt >> 1, pr = (nt & 1) * 2;
                            mma16816(acc[mt][nt], ah[mt], bh[g2][pr], bh[g2][pr + 1]);
                            mma16816(acc[mt][nt], ah[mt], bl[g2][pr], bl[g2][pr + 1]);
                            mma16816(acc[mt][nt], al[mt], bh[g2][pr], bh[g2][pr + 1]);
                        }
                }
            }
            __syncthreads();   // buffer reads done before next loads overwrite

            // ---- issue next loads ----
            if (ky < 2) {
                const int blk0 = (ocb * 9 + (ky + 1) * 3) * nkc + kc;
                for (int i = tid; i < 960; i += 256) {
                    int tap = i / 320, r = i - tap * 320;
                    long gsrc = (long)(blk0 + tap * nkc) * 320 + r;
                    uint32_t dB = BhU + (uint32_t)i * 16;
                    asm volatile("cp.async.cg.shared.global [%0], [%1], 16;"
                                 :: "r"(dB), "l"(Bh + gsrc) : "memory");
                    asm volatile("cp.async.cg.shared.global [%0], [%1], 16;"
                                 :: "r"(dB + 15360u), "l"(Bl + gsrc) : "memory");
                }
                asm volatile("cp.async.commit_group;" ::: "memory");
            } else if (kc + 1 < nkc) {
                const int kcn = kc + 1;
                for (int i = tid; i < totA; i += 256) {
                    int row = i >> 2, j = i & 3;
                    int seg = row / Wp2;
                    int px = x0 + (row - seg * Wp2) - 1;
                    int py = y0 + seg - 1;
                    bool ok = ((unsigned)px < (unsigned)W) && ((unsigned)py < (unsigned)H);
                    long src = (((long)n * H + py) * W + px) * CW4 + kcn * 4 + j;
                    uint32_t dA = AhU + (uint32_t)(row * 80 + j * 16);
                    int sz = ok ? 16 : 0;
                    asm volatile("cp.async.cg.shared.global [%0], [%1], 16, %2;"
                                 :: "r"(dA), "l"(inh + src), "r"(sz) : "memory");
                    asm volatile("cp.async.cg.shared.global [%0], [%1], 16, %2;"
                                 :: "r"(dA + (uint32_t)ABytes), "l"(inl + src), "r"(sz) : "memory");
                }
                const int blk0 = (ocb * 9) * nkc + kcn;
                for (int i = tid; i < 960; i += 256) {
                    int tap = i / 320, r = i - tap * 320;
                    long gsrc = (long)(blk0 + tap * nkc) * 320 + r;
                    uint32_t dB = BhU + (uint32_t)i * 16;
                    asm volatile("cp.async.cg.shared.global [%0], [%1], 16;"
                                 :: "r"(dB), "l"(Bh + gsrc) : "memory");
                    asm volatile("cp.async.cg.shared.global [%0], [%1], 16;"
                                 :: "r"(dB + 15360u), "l"(Bl + gsrc) : "memory");
                }
                asm volatile("cp.async.commit_group;" ::: "memory");
            }
        }
    }

    // ---- epilogue: stage ([oc][pixel], stride 132) ----
    {
        const int r0 = lane >> 2, cpair = (lane & 3) * 2;
#pragma unroll
        for (int mt = 0; mt < 2; mt++) {
            const int m1 = mbase + mt * 16 + r0, m2 = m1 + 8;
#pragma unroll
            for (int nt = 0; nt < 4; nt++) {
                const int nc = nbase + nt * 8 + cpair;
                stage[nc * 132 + m1]       = acc[mt][nt][0];
                stage[(nc + 1) * 132 + m1] = acc[mt][nt][1];
                stage[nc * 132 + m2]       = acc[mt][nt][2];
                stage[(nc + 1) * 132 + m2] = acc[mt][nt][3];
            }
        }
    }
    __syncthreads();
    // coalesced NCHW stores
    {
        const long HW = (long)H * W;
        const long obase = ((long)n * Cout + ocb * 64) * HW;
        for (int i = tid; i < 8192; i += 256) {
            int oc = i >> 7, p = i & 127;
            int y = y0 + (p >> TWsh), x = x0 + (p & (TW - 1));
            float v = fmaxf(stage[oc * 132 + p] * ss[oc] + bs[oc], 0.f);
            out[obase + (long)oc * HW + (long)y * W + x] = v;
        }
    }
    // fused 2x2 pool -> NHWC bf16 hi/lo (rpt==2 tiles only)
    if (ph) {
        const int Hp = H >> 1, Wp = W >> 1;
        const int yp = y0 >> 1, xp0 = x0 >> 1;
        for (int i = tid; i < 1024; i += 256) {
            int cw = i & 31, xx = i >> 5;
            int c0 = cw * 2, c1 = c0 + 1;
            int pa = 2 * xx, pc = TW + 2 * xx;
            float m0 = fmaxf(fmaxf(stage[c0 * 132 + pa], stage[c0 * 132 + pa + 1]),
                             fmaxf(stage[c0 * 132 + pc], stage[c0 * 132 + pc + 1]));
            float m1 = fmaxf(fmaxf(stage[c1 * 132 + pa], stage[c1 * 132 + pa + 1]),
                             fmaxf(stage[c1 * 132 + pc], stage[c1 * 132 + pc + 1]));
            float v0 = fmaxf(m0 * ss[c0] + bs[c0], 0.f);
            float v1 = fmaxf(m1 * ss[c1] + bs[c1], 0.f);
            uint32_t hw, lw;
            split2(v0, v1, hw, lw);
            long o = (((long)n * Hp + yp) * Wp + xp0 + xx) * poolCW + ocb * 32 + cw;
            ph[o] = hw; pl[o] = lw;
        }
    }
}

// ---------------- build per-channel quadratic form A = Re(U^H diag(zbar) U) --
__global__ void build_A_kernel(const float* __restrict__ w0,
                               const float* __restrict__ w1,
                               float* __restrict__ A)
{
    int t = blockIdx.x * blockDim.x + threadIdx.x;
    if (t >= 256 * 16) return;
    int c = t >> 4, k = t & 15;
    float gr[4][2][2], gi[4][2][2];
    float a0 = w0[c*2+0], a1 = w0[c*2+1], z0 = w1[c*2+0], z1 = w1[c*2+1];
    const float isq2 = 0.7071067811865476f;
#pragma unroll
    for (int w = 0; w < 4; w++) {
        float ay = (w & 1) ? a1 : a0, az = (w & 1) ? z1 : z0;
        float cy = cosf(ay*0.5f), sy = sinf(ay*0.5f);
        float cz = cosf(az*0.5f), sz = sinf(az*0.5f);
        float m00 = (cy-sy)*isq2, m01 = (cy+sy)*isq2;
        float m10 = (sy+cy)*isq2, m11 = (sy-cy)*isq2;
        gr[w][0][0]=m00*cz; gi[w][0][0]=-m00*sz;
        gr[w][0][1]=m01*cz; gi[w][0][1]=-m01*sz;
        gr[w][1][0]=m10*cz; gi[w][1][0]= m10*sz;
        gr[w][1][1]=m11*cz; gi[w][1][1]= m11*sz;
    }
    int P[16];
#pragma unroll
    for (int bb = 0; bb < 16; bb++) {
        int v = bb;
        if (v & 1) v ^= 8;
        if (v & 2) v ^= 1;
        if (v & 4) v ^= 2;
        if (v & 8) v ^= 4;
        P[bb] = v;
    }
    float acc[16];
#pragma unroll
    for (int j = 0; j < 16; j++) acc[j] = 0.f;
    for (int i = 0; i < 16; i++) {
        int r = P[i];
        float zi = (4 - 2 * __popc(i)) * 0.25f;
        int r0=(r>>3)&1, r1=(r>>2)&1, r2=(r>>1)&1, r3=r&1;
        float t2r[2], t2i[2];
        t2r[0]=gr[0][r0][0]; t2i[0]=gi[0][r0][0];
        t2r[1]=gr[0][r0][1]; t2i[1]=gi[0][r0][1];
        float t4r[4], t4i[4];
#pragma unroll
        for (int j0 = 0; j0 < 2; j0++)
#pragma unroll
            for (int j1 = 0; j1 < 2; j1++) {
                float br=gr[1][r1][j1], bi=gi[1][r1][j1];
                t4r[j0*2+j1]=t2r[j0]*br-t2i[j0]*bi;
                t4i[j0*2+j1]=t2r[j0]*bi+t2i[j0]*br;
            }
        float t8r[8], t8i[8];
#pragma unroll
        for (int j = 0; j < 4; j++)
#pragma unroll
            for (int j2 = 0; j2 < 2; j2++) {
                float br=gr[2][r2][j2], bi=gi[2][r2][j2];
                t8r[j*2+j2]=t4r[j]*br-t4i[j]*bi;
                t8i[j*2+j2]=t4r[j]*bi+t4i[j]*br;
            }
        float ur[16], ui[16];
#pragma unroll
        for (int j = 0; j < 8; j++)
#pragma unroll
            for (int j3 = 0; j3 < 2; j3++) {
                float br=gr[3][r3][j3], bi=gi[3][r3][j3];
                ur[j*2+j3]=t8r[j]*br-t8i[j]*bi;
                ui[j*2+j3]=t8r[j]*bi+t8i[j]*br;
            }
        float ukr = ur[k], uki = ui[k];
#pragma unroll
        for (int j = 0; j < 16; j++)
            acc[j] += zi * (ur[j]*ukr + ui[j]*uki);
    }
#pragma unroll
    for (int j = 0; j < 16; j++) A[c*256 + j*16 + k] = acc[j];
}

// ---------------- quantum stage + BN5 + ReLU (fused) -------------------------
__global__ __launch_bounds__(256) void quantum_kernel(
    const float* __restrict__ e4, const float* __restrict__ A,
    const float* __restrict__ g5, const float* __restrict__ b5,
    float* __restrict__ out)
{
    __shared__ float tile[35 * 37];
    __shared__ float As[256];
    const int bc = blockIdx.x, c = bc & 255, tid = threadIdx.x;
    for (int i = tid; i < 35 * 37; i += 256) tile[i] = 0.f;
    __syncthreads();
    const float* ep = e4 + (long)bc * 1024;
    for (int i = tid; i < 1024; i += 256) {
        int r = i >> 5, cc = i & 31;
        tile[(r + 1) * 37 + (cc + 1)] = ep[i];
    }
    if (tid < 256) As[tid] = A[c * 256 + tid];
    __syncthreads();
    const int y = tid >> 3, x4 = (tid & 7) * 4;
    float win[4][7];
#pragma unroll
    for (int r = 0; r < 4; r++)
#pragma unroll
        for (int cc = 0; cc < 7; cc++) win[r][cc] = tile[(y + r) * 37 + x4 + cc];
    float s[4] = {0.f, 0.f, 0.f, 0.f};
#pragma unroll
    for (int o = 0; o < 4; o++)
#pragma unroll
        for (int t = 0; t < 16; t++) {
            float v = win[t >> 2][(t & 3) + o];
            s[o] += v * v;
        }
    float quad[4] = {0.f, 0.f, 0.f, 0.f};
#pragma unroll
    for (int j = 0; j < 16; j++) {
        float t0 = 0.f, t1 = 0.f, t2 = 0.f, t3 = 0.f;
        int jr = j >> 2, jc = j & 3;
#pragma unroll
        for (int k = 0; k < 16; k++) {
            float a = As[j * 16 + k];
            int kr = k >> 2, kc = k & 3;
            t0 += a * win[kr][kc + 0];
            t1 += a * win[kr][kc + 1];
            t2 += a * win[kr][kc + 2];
            t3 += a * win[kr][kc + 3];
        }
        quad[0] += t0 * win[jr][jc + 0];
        quad[1] += t1 * win[jr][jc + 1];
        quad[2] += t2 * win[jr][jc + 2];
        quad[3] += t3 * win[jr][jc + 3];
    }
    const float sc = g5[c] * BN_INV, bb = b5[c];
    float4 v;
    v.x = fmaxf((0.5f*quad[0]/fmaxf(s[0],1e-24f)+0.5f)*sc+bb, 0.f);
    v.y = fmaxf((0.5f*quad[1]/fmaxf(s[1],1e-24f)+0.5f)*sc+bb, 0.f);
    v.z = fmaxf((0.5f*quad[2]/fmaxf(s[2],1e-24f)+0.5f)*sc+bb, 0.f);
    v.w = fmaxf((0.5f*quad[3]/fmaxf(s[3],1e-24f)+0.5f)*sc+bb, 0.f);
    *(float4*)(out + (long)bc * 1024 + y * 32 + x4) = v;
}

// -----------------------------------------------------------------------------
// dyn smem: conv2/3 73472, conv4 63872  (A: 2*(rpt+2)*(TW+2)*80, B: 30720, +512)
extern "C" void kernel_launch(void* const* d_in, const int* in_sizes, int n_in,
                              void* d_out, int out_size)
{
    (void)in_sizes; (void)n_in; (void)out_size;
    const float* x   = (const float*)d_in[0];
    const float* w1  = (const float*)d_in[1];
    const float* g1  = (const float*)d_in[2];
    const float* b1  = (const float*)d_in[3];
    const float* w2  = (const float*)d_in[4];
    const float* g2  = (const float*)d_in[5];
    const float* b2  = (const float*)d_in[6];
    const float* w3  = (const float*)d_in[7];
    const float* g3  = (const float*)d_in[8];
    const float* b3  = (const float*)d_in[9];
    const float* w4  = (const float*)d_in[10];
    const float* g4  = (const float*)d_in[11];
    const float* b4  = (const float*)d_in[12];
    const float* qw0 = (const float*)d_in[13];
    const float* qw1 = (const float*)d_in[14];
    const float* g5  = (const float*)d_in[15];
    const float* b5  = (const float*)d_in[16];

    float* out = (float*)d_out;
    float* e1 = out;
    float* e2 = out + 16777216;
    float* e3 = out + 25165824;
    float* o4 = out + 29360128;

    uint32_t *p1h, *p1l, *p2h, *p2l, *p3h, *p3l;
    uint16_t *B2h, *B2l, *B3h, *B3l, *B4h, *B4l;
    float *e4, *Ab;
    cudaGetSymbolAddress((void**)&p1h, g_p1h); cudaGetSymbolAddress((void**)&p1l, g_p1l);
    cudaGetSymbolAddress((void**)&p2h, g_p2h); cudaGetSymbolAddress((void**)&p2l, g_p2l);
    cudaGetSymbolAddress((void**)&p3h, g_p3h); cudaGetSymbolAddress((void**)&p3l, g_p3l);
    cudaGetSymbolAddress((void**)&B2h, g_B2h); cudaGetSymbolAddress((void**)&B2l, g_B2l);
    cudaGetSymbolAddress((void**)&B3h, g_B3h); cudaGetSymbolAddress((void**)&B3l, g_B3l);
    cudaGetSymbolAddress((void**)&B4h, g_B4h); cudaGetSymbolAddress((void**)&B4l, g_B4l);
    cudaGetSymbolAddress((void**)&e4, g_e4);   cudaGetSymbolAddress((void**)&Ab, g_A);

    cudaFuncSetAttribute(conv_mma_kernel, cudaFuncAttributeMaxDynamicSharedMemorySize, 73472);

    // conv1 + pool1 fused -> e1, p1
    conv1_pool_kernel<<<dim3(4, 16, 8), 256>>>(x, w1, g1, b1, e1, p1h, p1l);
    // weight packing (single launch)
    pack_all_kernel<<<1512, 256>>>(w2, w3, w4, B2h, B2l, B3h, B3l, B4h, B4l);
    // conv2 -> e2 (8,64,128,128), fused pool2 -> p2 (NHWC 64ch @64x64)
    conv_mma_kernel<<<dim3(128, 1, 8), 256, 73472>>>(
        (const uint4*)p1h, (const uint4*)p1l, (const uint4*)B2h, (const uint4*)B2l,
        g2, b2, e2, 128, 128, 6, 2, 4, 0, 64, 2, p2h, p2l, 32);
    // conv3 -> e3 (8,128,64,64), fused pool3 -> p3 (NHWC 128ch @32x32)
    conv_mma_kernel<<<dim3(32, 2, 8), 256, 73472>>>(
        (const uint4*)p2h, (const uint4*)p2l, (const uint4*)B3h, (const uint4*)B3l,
        g3, b3, e3, 64, 64, 6, 2, 8, 1, 128, 1, p3h, p3l, 64);
    // conv4 -> e4 (8,256,32,32), no pool
    conv_mma_kernel<<<dim3(8, 4, 8), 256, 63872>>>(
        (const uint4*)p3h, (const uint4*)p3l, (const uint4*)B4h, (const uint4*)B4l,
        g4, b4, e4, 32, 32, 5, 4, 16, 2, 256, 1, (uint32_t*)0, (uint32_t*)0, 0);
    // quantum
    build_A_kernel<<<16, 256>>>(qw0, qw1, Ab);
    quantum_kernel<<<2048, 256>>>(e4, Ab, g5, b5, o4);
}